// round 11
// baseline (speedup 1.0000x reference)
#include <cuda_runtime.h>
#include <math_constants.h>

#define BB 32
#define CC 64
#define HH 256
#define WW 256
#define HW (HH * WW)
#define TPB 256
#define HALF 8
#define INV_T 100.0f      // 1 / TEMPERATURE
#define PARTS 4           // streamer CTAs per channel
#define PART_F4 (HW / 4 / PARTS)   // float4 elems per part = 4096
#define WORKERS 32        // dedicated window CTAs (scheduled first, minimal slot tax)
#define NCH (BB * CC)
#define NPART (NCH * PARTS)

// per-(channel,part) packed argmax keys + per-channel arrival counters
__device__ unsigned long long g_keys[NPART];
__device__ unsigned int       g_cnt[NCH];   // zero-init; workers self-reset

// monotone float -> uint transform (order-preserving)
__device__ __forceinline__ unsigned int f2sortable(float f) {
    unsigned int u = __float_as_uint(f);
    return u ^ ((u & 0x80000000u) ? 0xFFFFFFFFu : 0x80000000u);
}
__device__ __forceinline__ float sortable2f(unsigned int u) {
    return __uint_as_float(u ^ ((u & 0x80000000u) ? 0x80000000u : 0xFFFFFFFFu));
}

__device__ __forceinline__ unsigned int ld_acquire_gpu(const unsigned int* p) {
    unsigned int v;
    asm volatile("ld.acquire.gpu.global.u32 %0, [%1];" : "=r"(v) : "l"(p) : "memory");
    return v;
}
__device__ __forceinline__ void red_release_gpu_add(unsigned int* p, unsigned int v) {
    asm volatile("red.release.gpu.global.add.u32 [%0], %1;" :: "l"(p), "r"(v) : "memory");
}

__device__ __forceinline__ unsigned long long umax64(unsigned long long a,
                                                     unsigned long long b) {
    return a > b ? a : b;
}

__global__ __launch_bounds__(TPB, 8)
void softargmax_ws2(const float* __restrict__ hm, float* __restrict__ out)
{
    const int tid  = threadIdx.x;
    const int warp = tid >> 5;
    const int lane = tid & 31;

    if (blockIdx.x >= WORKERS) {
        // ================= STREAMER: per-part argmax (bandwidth-bound) =================
        const int bid  = blockIdx.x - WORKERS;
        const int part = bid & (PARTS - 1);
        const int bc   = bid >> 2;

        const float4* __restrict__ base4 =
            (const float4*)(hm + (size_t)bc * HW) + part * PART_F4;

        float best = -CUDART_INF_F;
        int bidx = 0;

        #pragma unroll 4
        for (int i = tid; i < PART_F4; i += TPB) {
            float4 v = base4[i];
            if (v.x > best) { best = v.x; bidx = 4 * i + 0; }
            if (v.y > best) { best = v.y; bidx = 4 * i + 1; }
            if (v.z > best) { best = v.z; bidx = 4 * i + 2; }
            if (v.w > best) { best = v.w; bidx = 4 * i + 3; }
        }

        const int gidx = part * (HW / PARTS) + bidx;
        unsigned long long key =
            ((unsigned long long)f2sortable(best) << 32) | (unsigned int)(~gidx);

        // warp shuffle reduce (u64), then cross-warp via smem: 1 barrier total
        #pragma unroll
        for (int off = 16; off > 0; off >>= 1)
            key = umax64(key, __shfl_down_sync(0xFFFFFFFFu, key, off));

        __shared__ unsigned long long swk[TPB / 32];
        if (lane == 0) swk[warp] = key;
        __syncthreads();

        if (tid == 0) {
            unsigned long long k = swk[0];
            #pragma unroll
            for (int w = 1; w < TPB / 32; ++w) k = umax64(k, swk[w]);
            g_keys[bid] = k;
            // release-RED orders the key store before the counter increment
            red_release_gpu_add(&g_cnt[bc], 1u);
        }
        return;
    }

    // ================= WORKER: windowed softmax moments, overlapped =================
    __shared__ float red[TPB / 32][6];

    for (int ch = blockIdx.x; ch < NCH; ch += WORKERS) {
        if (tid == 0) {
            while (ld_acquire_gpu(&g_cnt[ch]) < PARTS) { /* spin */ }
        }
        __syncthreads();

        unsigned long long k = g_keys[ch * PARTS + 0];
        #pragma unroll
        for (int p = 1; p < PARTS; ++p)
            k = umax64(k, g_keys[ch * PARTS + p]);

        const float peak = sortable2f((unsigned int)(k >> 32));
        const int   idx  = (int)(~(unsigned int)k);
        const int   x0   = idx & (WW - 1);
        const int   y0   = idx >> 8;

        const int xmin = max(x0 - HALF, 0);
        const int xmax = min(x0 + HALF, WW);
        const int ymin = max(y0 - HALF, 0);
        const int ymax = min(y0 + HALF, HH);

        const int x = xmin + (tid & 15);
        const int y = ymin + (tid >> 4);

        const float* __restrict__ base = hm + (size_t)ch * HW;

        // moments centered at (x0, y0) to avoid cancellation
        float e = 0.f, edx = 0.f, edy = 0.f, edxx = 0.f, edyy = 0.f, edxy = 0.f;
        if (x < xmax && y < ymax) {
            float v  = base[y * WW + x];
            e        = __expf((v - peak) * INV_T);
            float dx = (float)(x - x0);
            float dy = (float)(y - y0);
            edx  = e * dx;
            edy  = e * dy;
            edxx = e * dx * dx;
            edyy = e * dy * dy;
            edxy = e * dx * dy;
        }

        float vals[6] = { e, edx, edy, edxx, edyy, edxy };
        #pragma unroll
        for (int off = 16; off > 0; off >>= 1) {
            #pragma unroll
            for (int kk = 0; kk < 6; ++kk)
                vals[kk] += __shfl_down_sync(0xFFFFFFFFu, vals[kk], off);
        }

        if (lane == 0) {
            #pragma unroll
            for (int kk = 0; kk < 6; ++kk) red[warp][kk] = vals[kk];
        }
        __syncthreads();

        if (tid == 0) {
            float S = 0.f, Sdx = 0.f, Sdy = 0.f, Sdxx = 0.f, Sdyy = 0.f, Sdxy = 0.f;
            #pragma unroll
            for (int w = 0; w < TPB / 32; ++w) {
                S    += red[w][0];
                Sdx  += red[w][1];
                Sdy  += red[w][2];
                Sdxx += red[w][3];
                Sdyy += red[w][4];
                Sdxy += red[w][5];
            }
            float inv = 1.0f / S;
            float mdx = Sdx * inv;
            float mdy = Sdy * inv;
            float x_mean = (float)x0 + mdx;
            float y_mean = (float)y0 + mdy;
            float var_xx = Sdxx * inv - mdx * mdx;
            float var_yy = Sdyy * inv - mdy * mdy;
            float cov_xy = Sdxy * inv - mdx * mdy;

            // output layout: coords (B,C,2) | cov (B,C,2,2) | spread (B,C,1)
            out[ch * 2 + 0] = x_mean * (1.0f / (WW - 1));
            out[ch * 2 + 1] = y_mean * (1.0f / (HH - 1));

            float* covp = out + NCH * 2;
            covp[ch * 4 + 0] = var_xx;
            covp[ch * 4 + 1] = cov_xy;
            covp[ch * 4 + 2] = cov_xy;
            covp[ch * 4 + 3] = var_yy;

            out[NCH * 6 + ch] = var_xx + var_yy;

            g_cnt[ch] = 0;   // self-reset for next graph replay
        }
        __syncthreads();   // protect shared `red` before next channel
    }
}

extern "C" void kernel_launch(void* const* d_in, const int* in_sizes, int n_in,
                              void* d_out, int out_size)
{
    const float* hm = (const float*)d_in[0];
    float* out = (float*)d_out;
    softargmax_ws2<<<WORKERS + NPART, TPB>>>(hm, out);
}

// round 12
// speedup vs baseline: 1.2652x; 1.2652x over previous
#include <cuda_runtime.h>
#include <math_constants.h>

#define BB 32
#define CC 64
#define HH 256
#define WW 256
#define HW (HH * WW)
#define TPB 256
#define HALF 8
#define INV_T 100.0f      // 1 / TEMPERATURE
#define PARTS 4           // streamer CTAs per channel
#define PART_F4 (HW / 4 / PARTS)   // float4 elems per part = 4096
#define WORKERS 16        // worker CTAs; each warp is an independent channel processor
#define NWARPW (WORKERS * (TPB / 32))   // 128 worker warps
#define NCH (BB * CC)
#define NPART (NCH * PARTS)

// per-(channel,part) packed argmax keys + per-channel arrival counters
__device__ unsigned long long g_keys[NPART];
__device__ unsigned int       g_cnt[NCH];   // zero-init; workers self-reset

// monotone float -> uint transform (order-preserving)
__device__ __forceinline__ unsigned int f2sortable(float f) {
    unsigned int u = __float_as_uint(f);
    return u ^ ((u & 0x80000000u) ? 0xFFFFFFFFu : 0x80000000u);
}
__device__ __forceinline__ float sortable2f(unsigned int u) {
    return __uint_as_float(u ^ ((u & 0x80000000u) ? 0x80000000u : 0xFFFFFFFFu));
}

__device__ __forceinline__ unsigned int ld_acquire_gpu(const unsigned int* p) {
    unsigned int v;
    asm volatile("ld.acquire.gpu.global.u32 %0, [%1];" : "=r"(v) : "l"(p) : "memory");
    return v;
}
__device__ __forceinline__ void red_release_gpu_add(unsigned int* p, unsigned int v) {
    asm volatile("red.release.gpu.global.add.u32 [%0], %1;" :: "l"(p), "r"(v) : "memory");
}

__device__ __forceinline__ unsigned long long umax64(unsigned long long a,
                                                     unsigned long long b) {
    return a > b ? a : b;
}

__global__ __launch_bounds__(TPB, 8)
void softargmax_wpc(const float* __restrict__ hm, float* __restrict__ out)
{
    const int tid  = threadIdx.x;
    const int warp = tid >> 5;
    const int lane = tid & 31;

    if (blockIdx.x >= WORKERS) {
        // ================= STREAMER: per-part argmax (bandwidth-bound) =================
        const int bid  = blockIdx.x - WORKERS;
        const int part = bid & (PARTS - 1);
        const int bc   = bid >> 2;

        const float4* __restrict__ base4 =
            (const float4*)(hm + (size_t)bc * HW) + part * PART_F4;

        float best = -CUDART_INF_F;
        int bidx = 0;

        #pragma unroll 4
        for (int i = tid; i < PART_F4; i += TPB) {
            float4 v = base4[i];
            if (v.x > best) { best = v.x; bidx = 4 * i + 0; }
            if (v.y > best) { best = v.y; bidx = 4 * i + 1; }
            if (v.z > best) { best = v.z; bidx = 4 * i + 2; }
            if (v.w > best) { best = v.w; bidx = 4 * i + 3; }
        }

        const int gidx = part * (HW / PARTS) + bidx;
        unsigned long long key =
            ((unsigned long long)f2sortable(best) << 32) | (unsigned int)(~gidx);

        // warp shuffle reduce (u64), then cross-warp via smem: 1 barrier total
        #pragma unroll
        for (int off = 16; off > 0; off >>= 1)
            key = umax64(key, __shfl_down_sync(0xFFFFFFFFu, key, off));

        __shared__ unsigned long long swk[TPB / 32];
        if (lane == 0) swk[warp] = key;
        __syncthreads();

        if (tid == 0) {
            unsigned long long k = swk[0];
            #pragma unroll
            for (int w = 1; w < TPB / 32; ++w) k = umax64(k, swk[w]);
            g_keys[bid] = k;
            // release-RED orders the key store before the counter increment
            red_release_gpu_add(&g_cnt[bc], 1u);
        }
        return;
    }

    // ============ WORKER: one warp = one independent channel processor ============
    const int gw = blockIdx.x * (TPB / 32) + warp;   // 0 .. NWARPW-1

    for (int ch = gw; ch < NCH; ch += NWARPW) {
        // all lanes spin on the counter (coalesced single-sector load)
        while (ld_acquire_gpu(&g_cnt[ch]) < PARTS) { /* spin */ }

        // lanes load the 4 part-keys in parallel, 2-step xor-shuffle max
        unsigned long long k = g_keys[ch * PARTS + (lane & 3)];
        k = umax64(k, __shfl_xor_sync(0xFFFFFFFFu, k, 1));
        k = umax64(k, __shfl_xor_sync(0xFFFFFFFFu, k, 2));

        const float peak = sortable2f((unsigned int)(k >> 32));
        const int   idx  = (int)(~(unsigned int)k);
        const int   x0   = idx & (WW - 1);
        const int   y0   = idx >> 8;

        const int xmin = max(x0 - HALF, 0);
        const int xmax = min(x0 + HALF, WW);
        const int ymin = max(y0 - HALF, 0);
        const int ymax = min(y0 + HALF, HH);

        const float* __restrict__ base = hm + (size_t)ch * HW;

        // each lane covers 8 cells of the 16x16 window: cell = lane + 32*j
        float e = 0.f, edx = 0.f, edy = 0.f, edxx = 0.f, edyy = 0.f, edxy = 0.f;
        #pragma unroll
        for (int j = 0; j < 8; ++j) {
            const int cell = lane + 32 * j;
            const int x = xmin + (cell & 15);
            const int y = ymin + (cell >> 4);
            if (x < xmax && y < ymax) {
                float v  = base[y * WW + x];
                float w  = __expf((v - peak) * INV_T);
                float dx = (float)(x - x0);
                float dy = (float)(y - y0);
                e    += w;
                edx  += w * dx;
                edy  += w * dy;
                edxx += w * dx * dx;
                edyy += w * dy * dy;
                edxy += w * dx * dy;
            }
        }

        // warp xor-shuffle reduce of the 6 moments
        float vals[6] = { e, edx, edy, edxx, edyy, edxy };
        #pragma unroll
        for (int off = 16; off > 0; off >>= 1) {
            #pragma unroll
            for (int kk = 0; kk < 6; ++kk)
                vals[kk] += __shfl_xor_sync(0xFFFFFFFFu, vals[kk], off);
        }

        if (lane == 0) {
            float inv = 1.0f / vals[0];
            float mdx = vals[1] * inv;
            float mdy = vals[2] * inv;
            float x_mean = (float)x0 + mdx;
            float y_mean = (float)y0 + mdy;
            float var_xx = vals[3] * inv - mdx * mdx;
            float var_yy = vals[4] * inv - mdy * mdy;
            float cov_xy = vals[5] * inv - mdx * mdy;

            // output layout: coords (B,C,2) | cov (B,C,2,2) | spread (B,C,1)
            out[ch * 2 + 0] = x_mean * (1.0f / (WW - 1));
            out[ch * 2 + 1] = y_mean * (1.0f / (HH - 1));

            float* covp = out + NCH * 2;
            covp[ch * 4 + 0] = var_xx;
            covp[ch * 4 + 1] = cov_xy;
            covp[ch * 4 + 2] = cov_xy;
            covp[ch * 4 + 3] = var_yy;

            out[NCH * 6 + ch] = var_xx + var_yy;

            g_cnt[ch] = 0;   // self-reset for next graph replay
        }
        __syncwarp();
    }
}

extern "C" void kernel_launch(void* const* d_in, const int* in_sizes, int n_in,
                              void* d_out, int out_size)
{
    const float* hm = (const float*)d_in[0];
    float* out = (float*)d_out;
    softargmax_wpc<<<WORKERS + NPART, TPB>>>(hm, out);
}

// round 14
// speedup vs baseline: 1.9137x; 1.5126x over previous
#include <cuda_runtime.h>
#include <math_constants.h>

#define BB 32
#define CC 64
#define HH 256
#define WW 256
#define HW (HH * WW)
#define TPB 256
#define HALF 8
#define INV_T 100.0f      // 1 / TEMPERATURE
#define PARTS 4           // streamer CTAs per channel
#define PART_F4 (HW / 4 / PARTS)   // float4 elems per part = 4096
#define NCH (BB * CC)
#define NPART (NCH * PARTS)
#define WPC_WARPS 8       // warps (channels) per CTA in the window kernel

// per-(channel,part) packed argmax keys
__device__ unsigned long long g_keys[NPART];

// monotone float -> uint transform (order-preserving)
__device__ __forceinline__ unsigned int f2sortable(float f) {
    unsigned int u = __float_as_uint(f);
    return u ^ ((u & 0x80000000u) ? 0xFFFFFFFFu : 0x80000000u);
}
__device__ __forceinline__ float sortable2f(unsigned int u) {
    return __uint_as_float(u ^ ((u & 0x80000000u) ? 0x80000000u : 0xFFFFFFFFu));
}
__device__ __forceinline__ unsigned long long umax64(unsigned long long a,
                                                     unsigned long long b) {
    return a > b ? a : b;
}

// ================= Kernel 1: streaming per-part argmax (bandwidth-bound) =================
__global__ __launch_bounds__(TPB, 8)
void argmax_part_kernel(const float* __restrict__ hm)
{
    const int tid  = threadIdx.x;
    const int warp = tid >> 5;
    const int lane = tid & 31;
    const int bid  = blockIdx.x;
    const int part = bid & (PARTS - 1);
    const int bc   = bid >> 2;

    const float4* __restrict__ base4 =
        (const float4*)(hm + (size_t)bc * HW) + part * PART_F4;

    float best = -CUDART_INF_F;
    int bidx = 0;

    #pragma unroll 4
    for (int i = tid; i < PART_F4; i += TPB) {
        float4 v = base4[i];
        if (v.x > best) { best = v.x; bidx = 4 * i + 0; }
        if (v.y > best) { best = v.y; bidx = 4 * i + 1; }
        if (v.z > best) { best = v.z; bidx = 4 * i + 2; }
        if (v.w > best) { best = v.w; bidx = 4 * i + 3; }
    }

    const int gidx = part * (HW / PARTS) + bidx;
    unsigned long long key =
        ((unsigned long long)f2sortable(best) << 32) | (unsigned int)(~gidx);

    // warp shuffle reduce (u64), then cross-warp via smem: 1 barrier total
    #pragma unroll
    for (int off = 16; off > 0; off >>= 1)
        key = umax64(key, __shfl_down_sync(0xFFFFFFFFu, key, off));

    __shared__ unsigned long long swk[TPB / 32];
    if (lane == 0) swk[warp] = key;
    __syncthreads();

    if (tid == 0) {
        unsigned long long k = swk[0];
        #pragma unroll
        for (int w = 1; w < TPB / 32; ++w) k = umax64(k, swk[w]);
        g_keys[bid] = k;
    }
}

// ================= Kernel 2: warp-per-channel windowed softmax moments =================
__global__ __launch_bounds__(WPC_WARPS * 32)
void window_kernel(const float* __restrict__ hm, float* __restrict__ out)
{
    const int warp = threadIdx.x >> 5;
    const int lane = threadIdx.x & 31;
    const int ch   = blockIdx.x * WPC_WARPS + warp;   // one warp = one channel

    // lanes load the 4 part-keys in parallel, 2-step xor-shuffle max
    unsigned long long k = g_keys[ch * PARTS + (lane & 3)];
    k = umax64(k, __shfl_xor_sync(0xFFFFFFFFu, k, 1));
    k = umax64(k, __shfl_xor_sync(0xFFFFFFFFu, k, 2));

    const float peak = sortable2f((unsigned int)(k >> 32));
    const int   idx  = (int)(~(unsigned int)k);
    const int   x0   = idx & (WW - 1);
    const int   y0   = idx >> 8;

    const int xmin = max(x0 - HALF, 0);
    const int xmax = min(x0 + HALF, WW);
    const int ymin = max(y0 - HALF, 0);
    const int ymax = min(y0 + HALF, HH);

    const float* __restrict__ base = hm + (size_t)ch * HW;

    // each lane covers 8 cells of the 16x16 window (MLP=8 independent loads)
    float e = 0.f, edx = 0.f, edy = 0.f, edxx = 0.f, edyy = 0.f, edxy = 0.f;
    #pragma unroll
    for (int j = 0; j < 8; ++j) {
        const int cell = lane + 32 * j;
        const int x = xmin + (cell & 15);
        const int y = ymin + (cell >> 4);
        if (x < xmax && y < ymax) {
            float v  = base[y * WW + x];
            float w  = __expf((v - peak) * INV_T);
            float dx = (float)(x - x0);
            float dy = (float)(y - y0);
            e    += w;
            edx  += w * dx;
            edy  += w * dy;
            edxx += w * dx * dx;
            edyy += w * dy * dy;
            edxy += w * dx * dy;
        }
    }

    // warp xor-shuffle reduce of the 6 moments
    float vals[6] = { e, edx, edy, edxx, edyy, edxy };
    #pragma unroll
    for (int off = 16; off > 0; off >>= 1) {
        #pragma unroll
        for (int kk = 0; kk < 6; ++kk)
            vals[kk] += __shfl_xor_sync(0xFFFFFFFFu, vals[kk], off);
    }

    if (lane == 0) {
        float inv = 1.0f / vals[0];
        float mdx = vals[1] * inv;
        float mdy = vals[2] * inv;
        float x_mean = (float)x0 + mdx;
        float y_mean = (float)y0 + mdy;
        float var_xx = vals[3] * inv - mdx * mdx;
        float var_yy = vals[4] * inv - mdy * mdy;
        float cov_xy = vals[5] * inv - mdx * mdy;

        // output layout: coords (B,C,2) | cov (B,C,2,2) | spread (B,C,1)
        out[ch * 2 + 0] = x_mean * (1.0f / (WW - 1));
        out[ch * 2 + 1] = y_mean * (1.0f / (HH - 1));

        float* covp = out + NCH * 2;
        covp[ch * 4 + 0] = var_xx;
        covp[ch * 4 + 1] = cov_xy;
        covp[ch * 4 + 2] = cov_xy;
        covp[ch * 4 + 3] = var_yy;

        out[NCH * 6 + ch] = var_xx + var_yy;
    }
}

extern "C" void kernel_launch(void* const* d_in, const int* in_sizes, int n_in,
                              void* d_out, int out_size)
{
    const float* hm = (const float*)d_in[0];
    float* out = (float*)d_out;
    argmax_part_kernel<<<NPART, TPB>>>(hm);
    window_kernel<<<NCH / WPC_WARPS, WPC_WARPS * 32>>>(hm, out);
}

// round 15
// speedup vs baseline: 1.9294x; 1.0082x over previous
#include <cuda_runtime.h>
#include <math_constants.h>

#define BB 32
#define CC 64
#define HH 256
#define WW 256
#define HW (HH * WW)
#define TPB 256
#define HALF 8
#define INV_T 100.0f      // 1 / TEMPERATURE
#define PARTS 4           // streamer CTAs per channel
#define PART_F4 (HW / 4 / PARTS)   // float4 elems per part = 4096
#define NCH (BB * CC)
#define NPART (NCH * PARTS)
#define WPC_WARPS 16      // warps (channels) per CTA in window kernel -> 128 CTAs = 1 wave

// per-(channel,part) packed argmax keys
__device__ unsigned long long g_keys[NPART];

// monotone float -> uint transform (order-preserving)
__device__ __forceinline__ unsigned int f2sortable(float f) {
    unsigned int u = __float_as_uint(f);
    return u ^ ((u & 0x80000000u) ? 0xFFFFFFFFu : 0x80000000u);
}
__device__ __forceinline__ float sortable2f(unsigned int u) {
    return __uint_as_float(u ^ ((u & 0x80000000u) ? 0x80000000u : 0xFFFFFFFFu));
}
__device__ __forceinline__ unsigned long long umax64(unsigned long long a,
                                                     unsigned long long b) {
    return a > b ? a : b;
}

// ================= Kernel 1: streaming per-part argmax (bandwidth-bound) =================
__global__ __launch_bounds__(TPB, 8)
void argmax_part_kernel(const float* __restrict__ hm)
{
    const int tid  = threadIdx.x;
    const int warp = tid >> 5;
    const int lane = tid & 31;
    const int bid  = blockIdx.x;
    const int part = bid & (PARTS - 1);
    const int bc   = bid >> 2;

    const float4* __restrict__ base4 =
        (const float4*)(hm + (size_t)bc * HW) + part * PART_F4;

    float best = -CUDART_INF_F;
    int bidx = 0;

    #pragma unroll 4
    for (int i = tid; i < PART_F4; i += TPB) {
        float4 v = base4[i];
        if (v.x > best) { best = v.x; bidx = 4 * i + 0; }
        if (v.y > best) { best = v.y; bidx = 4 * i + 1; }
        if (v.z > best) { best = v.z; bidx = 4 * i + 2; }
        if (v.w > best) { best = v.w; bidx = 4 * i + 3; }
    }

    const int gidx = part * (HW / PARTS) + bidx;
    unsigned long long key =
        ((unsigned long long)f2sortable(best) << 32) | (unsigned int)(~gidx);

    // warp shuffle reduce (u64), then cross-warp via smem: 1 barrier total
    #pragma unroll
    for (int off = 16; off > 0; off >>= 1)
        key = umax64(key, __shfl_down_sync(0xFFFFFFFFu, key, off));

    __shared__ unsigned long long swk[TPB / 32];
    if (lane == 0) swk[warp] = key;
    __syncthreads();

    if (tid == 0) {
        unsigned long long k = swk[0];
        #pragma unroll
        for (int w = 1; w < TPB / 32; ++w) k = umax64(k, swk[w]);
        g_keys[bid] = k;
    }
}

// ====== Kernel 2: warp-per-channel windowed softmax moments (single CTA wave) ======
__global__ __launch_bounds__(WPC_WARPS * 32)
void window_kernel(const float* __restrict__ hm, float* __restrict__ out)
{
    const int warp = threadIdx.x >> 5;
    const int lane = threadIdx.x & 31;
    const int ch   = blockIdx.x * WPC_WARPS + warp;   // one warp = one channel

    // lanes load the 4 part-keys in parallel, 2-step xor-shuffle max
    unsigned long long k = g_keys[ch * PARTS + (lane & 3)];
    k = umax64(k, __shfl_xor_sync(0xFFFFFFFFu, k, 1));
    k = umax64(k, __shfl_xor_sync(0xFFFFFFFFu, k, 2));

    const float peak = sortable2f((unsigned int)(k >> 32));
    const int   idx  = (int)(~(unsigned int)k);
    const int   x0   = idx & (WW - 1);
    const int   y0   = idx >> 8;

    const int xmin = max(x0 - HALF, 0);
    const int xmax = min(x0 + HALF, WW);
    const int ymin = max(y0 - HALF, 0);
    const int ymax = min(y0 + HALF, HH);

    const float* __restrict__ base = hm + (size_t)ch * HW;

    // each lane covers 8 cells of the 16x16 window (MLP=8 independent loads)
    float e = 0.f, edx = 0.f, edy = 0.f, edxx = 0.f, edyy = 0.f, edxy = 0.f;
    #pragma unroll
    for (int j = 0; j < 8; ++j) {
        const int cell = lane + 32 * j;
        const int x = xmin + (cell & 15);
        const int y = ymin + (cell >> 4);
        if (x < xmax && y < ymax) {
            float v  = base[y * WW + x];
            float w  = __expf((v - peak) * INV_T);
            float dx = (float)(x - x0);
            float dy = (float)(y - y0);
            e    += w;
            edx  += w * dx;
            edy  += w * dy;
            edxx += w * dx * dx;
            edyy += w * dy * dy;
            edxy += w * dx * dy;
        }
    }

    // warp xor-shuffle reduce of the 6 moments
    float vals[6] = { e, edx, edy, edxx, edyy, edxy };
    #pragma unroll
    for (int off = 16; off > 0; off >>= 1) {
        #pragma unroll
        for (int kk = 0; kk < 6; ++kk)
            vals[kk] += __shfl_xor_sync(0xFFFFFFFFu, vals[kk], off);
    }

    if (lane == 0) {
        float inv = 1.0f / vals[0];
        float mdx = vals[1] * inv;
        float mdy = vals[2] * inv;
        float x_mean = (float)x0 + mdx;
        float y_mean = (float)y0 + mdy;
        float var_xx = vals[3] * inv - mdx * mdx;
        float var_yy = vals[4] * inv - mdy * mdy;
        float cov_xy = vals[5] * inv - mdx * mdy;

        // output layout: coords (B,C,2) | cov (B,C,2,2) | spread (B,C,1)
        out[ch * 2 + 0] = x_mean * (1.0f / (WW - 1));
        out[ch * 2 + 1] = y_mean * (1.0f / (HH - 1));

        float* covp = out + NCH * 2;
        covp[ch * 4 + 0] = var_xx;
        covp[ch * 4 + 1] = cov_xy;
        covp[ch * 4 + 2] = cov_xy;
        covp[ch * 4 + 3] = var_yy;

        out[NCH * 6 + ch] = var_xx + var_yy;
    }
}

extern "C" void kernel_launch(void* const* d_in, const int* in_sizes, int n_in,
                              void* d_out, int out_size)
{
    const float* hm = (const float*)d_in[0];
    float* out = (float*)d_out;
    argmax_part_kernel<<<NPART, TPB>>>(hm);
    window_kernel<<<NCH / WPC_WARPS, WPC_WARPS * 32>>>(hm, out);
}